// round 10
// baseline (speedup 1.0000x reference)
#include <cuda_runtime.h>
#include <math.h>
#include <stdint.h>

#define C 64
#define P (512 * 512)
#define K 20
#define NUM_CLASSES 11
#define EPS 1e-8f

#define NBLOCK 512
#define PPB (P / NBLOCK)        // 512 pixels per block
#define TK 64                   // pixels per MMA tile
#define NT (PPB / TK)           // 8 tiles

#define ASTRIDE 68              // padded row stride: MMA-frag LDS conflict-free
#define A_FLOATS (128 * ASTRIDE)
#define RED_FLOATS 2048         // aliased: s_red1|s_red2 (2048) / s_bf (24*68=1632)
#define DYN_SZ ((A_FLOATS + RED_FLOATS) * 4)   // 43008 B < 48K default limit

// partials: sum1[20][64] | usum[20][64] | cnt[20] | sq[20]
#define PART_STRIDE 2600
#define OFF_SUM1 0
#define OFF_USUM 1280
#define OFF_CNT 2560
#define OFF_SQ 2580

static __device__ float g_part[NBLOCK * PART_STRIDE];
static __device__ float g_red[PART_STRIDE];
static __device__ unsigned int g_ticket;   // zero-init; self-resetting

// tf32 m16n8k8 row.col MMA (sm_80+, works at compute_100)
__device__ __forceinline__ void mma_tf32(float& d0, float& d1, float& d2, float& d3,
                                         uint32_t a0, uint32_t a1, uint32_t a2, uint32_t a3,
                                         uint32_t b0, uint32_t b1)
{
    asm volatile(
        "mma.sync.aligned.m16n8k8.row.col.f32.tf32.tf32.f32 "
        "{%0,%1,%2,%3}, {%4,%5,%6,%7}, {%8,%9}, {%0,%1,%2,%3};"
        : "+f"(d0), "+f"(d1), "+f"(d2), "+f"(d3)
        : "r"(a0), "r"(a1), "r"(a2), "r"(a3), "r"(b0), "r"(b1));
}

__device__ __forceinline__ void hi_lo(float v, uint32_t& h, uint32_t& l)
{
    uint32_t hu = __float_as_uint(v) & 0xFFFFE000u;   // tf32 truncation
    h = hu;
    l = __float_as_uint(v - __uint_as_float(hu));     // residual
}

// ---------------------------------------------------------------------------
// Main pass: warp-tiled tf32 MMA, software-pipelined, 3 CTAs/SM target.
// D[128][24] = A · B^T over K = 512 pixels (8 tiles of 64).
// A rows 0-63 = v1 channels, 64-127 = normalized v2 channels.
// Prefetch in regs: v1 quads + mask ints for t+1. v2 loaded at Phase A start
// (latency hidden by other resident warps). s_red (A-B) aliases s_bf (C-D).
// ---------------------------------------------------------------------------
__global__ void __launch_bounds__(256, 3)
main_pass(const float* __restrict__ v1g,
          const float* __restrict__ v2g,
          const int* __restrict__ masks)
{
    extern __shared__ float dyn[];
    float* s_a    = dyn;                       // [128][68]
    float* s_red1 = dyn + A_FLOATS;            // [1024]   (Phase A-B)
    float* s_red2 = dyn + A_FLOATS + 1024;     // [1024]   (Phase A-B)
    float* s_bf   = dyn + A_FLOATS;            // [24][68] (Phase C-D, aliases s_red)

    __shared__ float s_s1[64];
    __shared__ float s_inv[64];

    const int tid = threadIdx.x;
    const int wid = tid >> 5;
    const int lane = tid & 31;
    const int g  = lane >> 2;     // 0..7
    const int tg = lane & 3;      // 0..3
    const int f4 = tid & 15;      // pixel quad
    const int cr = tid >> 4;      // channel row group

    float acc[3][4];
#pragma unroll
    for (int nt = 0; nt < 3; ++nt)
#pragma unroll
        for (int q = 0; q < 4; ++q) acc[nt][q] = 0.f;

    float cntAcc = 0.f, sqAcc = 0.f;
    const size_t p0base = (size_t)blockIdx.x * PPB;
    const int rowA0 = 16 * wid + g;

    // ---- prologue: prefetch tile 0 (v1 + masks) ---------------------------
    float4 av[4];
    int mreg[5];
#pragma unroll
    for (int i = 0; i < 4; ++i)
        av[i] = *(const float4*)(v1g + (size_t)(cr + 16 * i) * P + p0base + 4 * f4);
#pragma unroll
    for (int r = 0; r < 5; ++r) {
        int e = tid + 256 * r;
        mreg[r] = masks[(size_t)(e >> 6) * P + p0base + (e & 63)];
    }

    for (int t = 0; t < NT; ++t) {
        const size_t p0 = p0base + (size_t)t * TK;
        const size_t p1 = p0 + TK;
        __syncthreads();   // prev tile's MMA/cnt reads done: s_a, s_bf free

        // ---- Phase A: v2 loads first (overlap), consume v1, prefetch v1 ---
        float4 bv[4];
#pragma unroll
        for (int i = 0; i < 4; ++i)
            bv[i] = *(const float4*)(v2g + (size_t)(cr + 16 * i) * P + p0 + 4 * f4);

        float4 pp1 = make_float4(0.f, 0.f, 0.f, 0.f);
#pragma unroll
        for (int i = 0; i < 4; ++i) {
            int c = cr + 16 * i;
            float4 a = av[i];
            pp1.x = fmaf(a.x, a.x, pp1.x); pp1.y = fmaf(a.y, a.y, pp1.y);
            pp1.z = fmaf(a.z, a.z, pp1.z); pp1.w = fmaf(a.w, a.w, pp1.w);
            *(float4*)&s_a[c * ASTRIDE + 4 * f4] = a;
        }
        *(float4*)&s_red1[tid * 4] = pp1;

        if (t + 1 < NT) {
#pragma unroll
            for (int i = 0; i < 4; ++i)
                av[i] = *(const float4*)(v1g + (size_t)(cr + 16 * i) * P + p1 + 4 * f4);
        }

        float4 pp2 = make_float4(0.f, 0.f, 0.f, 0.f);
#pragma unroll
        for (int i = 0; i < 4; ++i) {
            int c = cr + 16 * i;
            float4 b = bv[i];
            pp2.x = fmaf(b.x, b.x, pp2.x); pp2.y = fmaf(b.y, b.y, pp2.y);
            pp2.z = fmaf(b.z, b.z, pp2.z); pp2.w = fmaf(b.w, b.w, pp2.w);
            *(float4*)&s_a[(64 + c) * ASTRIDE + 4 * f4] = b;   // raw v2
        }
        *(float4*)&s_red2[tid * 4] = pp2;
        __syncthreads();

        // ---- Phase B: reduce per-pixel norms (64 threads) -----------------
        if (tid < TK) {
            int q = tid >> 2, cm = tid & 3;
            float s1 = 0.f, s2 = 0.f;
#pragma unroll
            for (int r = 0; r < 16; ++r) {
                s1 += s_red1[(r * 16 + q) * 4 + cm];
                s2 += s_red2[(r * 16 + q) * 4 + cm];
            }
            s_s1[tid]  = s1;
            s_inv[tid] = 1.0f / fmaxf(sqrtf(s2), EPS);
        }
        __syncthreads();

        // ---- Phase C: rescale v2 in place; build B tile; prefetch masks ---
        {
            float4 iv = *(const float4*)&s_inv[4 * f4];
#pragma unroll
            for (int i = 0; i < 4; ++i) {
                int c = cr + 16 * i;
                float4 b = *(const float4*)&s_a[(64 + c) * ASTRIDE + 4 * f4];
                b.x *= iv.x; b.y *= iv.y; b.z *= iv.z; b.w *= iv.w;
                *(float4*)&s_a[(64 + c) * ASTRIDE + 4 * f4] = b;
            }
        }
#pragma unroll
        for (int r = 0; r < 5; ++r) {
            int e = tid + 256 * r;
            s_bf[(e >> 6) * ASTRIDE + (e & 63)] = (float)(mreg[r] & 1);
        }
        // zero pad rows 20..23 (aliased region clobbered every tile)
        s_bf[(20 + (tid >> 6)) * ASTRIDE + (tid & 63)] = 0.f;

        if (t + 1 < NT) {
#pragma unroll
            for (int r = 0; r < 5; ++r) {
                int e = tid + 256 * r;
                mreg[r] = masks[(size_t)(e >> 6) * P + p1 + (e & 63)];
            }
        }
        __syncthreads();

        // ---- Phase D: MMA over 8 k-steps; cnt/sq on warp 0 ---------------
#pragma unroll
        for (int s = 0; s < 8; ++s) {
            int c0 = 8 * s + tg;
            int c1 = c0 + 4;
            float ra0 = s_a[rowA0 * ASTRIDE + c0];
            float ra1 = s_a[(rowA0 + 8) * ASTRIDE + c0];
            float ra2 = s_a[rowA0 * ASTRIDE + c1];
            float ra3 = s_a[(rowA0 + 8) * ASTRIDE + c1];
            uint32_t h0, l0, h1, l1, h2, l2, h3, l3;
            hi_lo(ra0, h0, l0); hi_lo(ra1, h1, l1);
            hi_lo(ra2, h2, l2); hi_lo(ra3, h3, l3);
#pragma unroll
            for (int nt = 0; nt < 3; ++nt) {
                int n0 = 8 * nt + g;
                uint32_t b0 = __float_as_uint(s_bf[n0 * ASTRIDE + c0]);
                uint32_t b1 = __float_as_uint(s_bf[n0 * ASTRIDE + c1]);
                mma_tf32(acc[nt][0], acc[nt][1], acc[nt][2], acc[nt][3],
                         h0, h1, h2, h3, b0, b1);
                mma_tf32(acc[nt][0], acc[nt][1], acc[nt][2], acc[nt][3],
                         l0, l1, l2, l3, b0, b1);
            }
        }
        if (tid < K) {
            float c0 = 0.f, s0 = 0.f;
#pragma unroll 8
            for (int p = 0; p < TK; ++p) {
                float m = s_bf[tid * ASTRIDE + p];
                c0 += m;
                s0 = fmaf(m, s_s1[p], s0);
            }
            cntAcc += c0;
            sqAcc  += s0;
        }
    }

    // ---- epilogue: accumulators -> per-block partials ---------------------
    float* base = g_part + (size_t)blockIdx.x * PART_STRIDE;
    {
        int m0 = rowA0;
        int m1 = rowA0 + 8;
        int off0 = (m0 < 64) ? (OFF_SUM1 + m0) : (OFF_USUM + (m0 - 64));
        int off1 = (m1 < 64) ? (OFF_SUM1 + m1) : (OFF_USUM + (m1 - 64));
#pragma unroll
        for (int nt = 0; nt < 3; ++nt) {
            int n0 = 8 * nt + 2 * tg;
            if (n0 < K)     base[off0 + n0 * C]       = acc[nt][0];
            if (n0 + 1 < K) base[off0 + (n0 + 1) * C] = acc[nt][1];
            if (n0 < K)     base[off1 + n0 * C]       = acc[nt][2];
            if (n0 + 1 < K) base[off1 + (n0 + 1) * C] = acc[nt][3];
        }
    }
    if (tid < K) {
        base[OFF_CNT + tid] = cntAcc;
        base[OFF_SQ  + tid] = sqAcc;
    }
}

// ---------------------------------------------------------------------------
// Reduce + finalize (fused): blocks reduce 16 indices each (coalesced, fixed
// order); the LAST block (threadfence ticket) runs the finalize math.
// Deterministic: finalize reads fully-written g_red in fixed order.
// ---------------------------------------------------------------------------
#define RF_BLOCKS ((PART_STRIDE + 15) / 16)   // 163

__global__ void __launch_bounds__(256, 8)
reduce_finalize(const int* __restrict__ labels, float* __restrict__ out)
{
    __shared__ float s[16][17];
    __shared__ unsigned int isLast;

    const int tid = threadIdx.x;
    const int il = tid & 15;
    const int br = tid >> 4;
    const int i  = blockIdx.x * 16 + il;

    float acc = 0.f;
    if (i < PART_STRIDE) {
#pragma unroll 4
        for (int j = 0; j < NBLOCK / 16; ++j)
            acc += g_part[(size_t)(br + 16 * j) * PART_STRIDE + i];
    }
    s[br][il] = acc;
    __syncthreads();

    if (tid < 16) {
        const int ii = blockIdx.x * 16 + tid;
        if (ii < PART_STRIDE) {
            float t = 0.f;
#pragma unroll
            for (int b = 0; b < 16; ++b) t += s[b][tid];
            g_red[ii] = t;
        }
    }
    __syncthreads();

    if (tid == 0) {
        __threadfence();
        unsigned int tk = atomicAdd(&g_ticket, 1u);
        isLast = (tk == (unsigned int)(RF_BLOCKS - 1)) ? 1u : 0u;
    }
    __syncthreads();
    if (!isLast) return;
    __threadfence();

    // ---------------- finalize (single block, 256 threads) -----------------
    __shared__ float S[PART_STRIDE];
    __shared__ float m1n[K * C];
    __shared__ float simm[K * K];
    __shared__ float stdv[K];
    __shared__ int   s_cls[K];

    for (int ii = tid; ii < PART_STRIDE; ii += 256) S[ii] = g_red[ii];
    if (tid < K) s_cls[tid] = labels[tid];
    __syncthreads();

    if (tid < K) {
        const int k = tid;
        float cnt = S[OFF_CNT + k];
        float rc  = 1.0f / cnt;
        float ssum = 0.f;
        for (int cc = 0; cc < C; ++cc) ssum += S[OFF_SUM1 + k * C + cc];
        float n_elem = cnt * (float)C;
        float em  = ssum / n_elem;
        float var = (S[OFF_SQ + k] - n_elem * em * em) / (n_elem - 1.0f);
        stdv[k] = sqrtf(fmaxf(var, 0.0f));

        float nrm2 = 0.f;
        for (int cc = 0; cc < C; ++cc) {
            float m = S[OFF_SUM1 + k * C + cc] * rc;
            m1n[k * C + cc] = m;
            nrm2 = fmaf(m, m, nrm2);
        }
        float inv = 1.0f / fmaxf(sqrtf(nrm2), EPS);
        for (int cc = 0; cc < C; ++cc) m1n[k * C + cc] *= inv;
        for (int cc = 0; cc < C; ++cc) S[OFF_USUM + k * C + cc] *= rc;
    }
    __syncthreads();

    for (int e = tid; e < K * K; e += 256) {
        int ki = e / K;
        int kj = e % K;
        float d = 0.f;
#pragma unroll 8
        for (int cc = 0; cc < C; ++cc)
            d = fmaf(m1n[ki * C + cc], S[OFF_USUM + kj * C + cc], d);
        simm[e] = d;
    }
    __syncthreads();

    if (tid < 32) {
        float ns = 0.f, nc = 0.f;
        for (int e = tid; e < K * K; e += 32) {
            int ki = e / K, kj = e % K;
            if (s_cls[ki] != s_cls[kj]) { ns += simm[e]; nc += 1.0f; }
        }
#pragma unroll
        for (int off = 16; off > 0; off >>= 1) {
            ns += __shfl_xor_sync(0xFFFFFFFFu, ns, off);
            nc += __shfl_xor_sync(0xFFFFFFFFu, nc, off);
        }
        if (tid == 0) out[22] = ns / nc;
    } else if (tid >= 64 && tid < 64 + NUM_CLASSES) {
        const int cl = tid - 64;
        float inst = 0.f, st = 0.f, cs = 0.f, cnt = 0.f;
        for (int ki = 0; ki < K; ++ki) {
            if (s_cls[ki] == cl) {
                inst += simm[ki * K + ki];
                st   += stdv[ki];
                cnt  += 1.0f;
                for (int kj = 0; kj < K; ++kj)
                    if (kj != ki && s_cls[kj] == cl) cs += simm[ki * K + kj];
            }
        }
        if (cnt > 1.0f) {
            inst /= cnt;
            cs   /= cnt * (cnt - 1.0f);
            st   /= cnt;
        }
        out[cl]      = inst;
        out[11 + cl] = cs;
        out[23 + cl] = st;
    }
    __syncthreads();
    if (tid == 0) g_ticket = 0u;   // reset for next graph replay
}

extern "C" void kernel_launch(void* const* d_in, const int* in_sizes, int n_in,
                              void* d_out, int out_size)
{
    const float* v1     = (const float*)d_in[0];
    const float* v2     = (const float*)d_in[1];
    const int*   labels = (const int*)d_in[2];
    const int*   masks  = (const int*)d_in[3];
    float* out = (float*)d_out;

    main_pass<<<NBLOCK, 256, DYN_SZ>>>(v1, v2, masks);
    reduce_finalize<<<RF_BLOCKS, 256>>>(labels, out);
}

// round 11
// speedup vs baseline: 1.1725x; 1.1725x over previous
#include <cuda_runtime.h>
#include <math.h>
#include <stdint.h>

#define C 64
#define P (512 * 512)
#define K 20
#define NUM_CLASSES 11
#define EPS 1e-8f

#define NBLOCK 256
#define PPB (P / NBLOCK)        // 1024 pixels per block
#define TK 64                   // pixels per MMA tile
#define NT (PPB / TK)           // 16 tiles

#define ASTRIDE 68              // padded row stride: MMA-frag LDS conflict-free
#define A_FLOATS (128 * ASTRIDE)
#define RED_FLOATS 2048         // aliased: s_red1|s_red2 (2048) / s_bf (24*68=1632)
#define DYN_SZ ((A_FLOATS + RED_FLOATS) * 4)   // 43008 B < 48K default limit

// reduced sums: sum1[20][64] | usum[20][64] | cnt[20] | sq[20]
#define PART_STRIDE 2600
#define OFF_SUM1 0
#define OFF_USUM 1280
#define OFF_CNT 2560
#define OFF_SQ 2580

static __device__ float g_red[PART_STRIDE];   // zero-init; finalize re-zeroes

// tf32 m16n8k8 row.col MMA (sm_80+, works at compute_100)
__device__ __forceinline__ void mma_tf32(float& d0, float& d1, float& d2, float& d3,
                                         uint32_t a0, uint32_t a1, uint32_t a2, uint32_t a3,
                                         uint32_t b0, uint32_t b1)
{
    asm volatile(
        "mma.sync.aligned.m16n8k8.row.col.f32.tf32.tf32.f32 "
        "{%0,%1,%2,%3}, {%4,%5,%6,%7}, {%8,%9}, {%0,%1,%2,%3};"
        : "+f"(d0), "+f"(d1), "+f"(d2), "+f"(d3)
        : "r"(a0), "r"(a1), "r"(a2), "r"(a3), "r"(b0), "r"(b1));
}

__device__ __forceinline__ void hi_lo(float v, uint32_t& h, uint32_t& l)
{
    uint32_t hu = __float_as_uint(v) & 0xFFFFE000u;   // tf32 truncation
    h = hu;
    l = __float_as_uint(v - __uint_as_float(hu));     // residual
}

// ---------------------------------------------------------------------------
// Main pass: warp-tiled tf32 MMA, software-pipelined (identical to the 50.8us
// R9 kernel). D[128][24] = A · B^T over K = 1024 pixels (16 tiles of 64).
// A rows 0-63 = v1 channels, 64-127 = normalized v2 channels.
// Epilogue: atomicAdd directly into g_red (no per-block partial buffer).
// ---------------------------------------------------------------------------
__global__ void __launch_bounds__(256, 2)
main_pass(const float* __restrict__ v1g,
          const float* __restrict__ v2g,
          const int* __restrict__ masks)
{
    extern __shared__ float dyn[];
    float* s_a    = dyn;                       // [128][68]
    float* s_red1 = dyn + A_FLOATS;            // [1024]   (Phase A-B)
    float* s_red2 = dyn + A_FLOATS + 1024;     // [1024]   (Phase A-B)
    float* s_bf   = dyn + A_FLOATS;            // [24][68] (Phase C-D, aliases s_red)

    __shared__ float s_s1[64];
    __shared__ float s_inv[64];

    const int tid = threadIdx.x;
    const int wid = tid >> 5;
    const int lane = tid & 31;
    const int g  = lane >> 2;     // 0..7
    const int tg = lane & 3;      // 0..3
    const int f4 = tid & 15;      // pixel quad
    const int cr = tid >> 4;      // channel row group

    int mk[5], mp[5];
#pragma unroll
    for (int r = 0; r < 5; ++r) {
        int e = tid + 256 * r;
        mk[r] = e >> 6;
        mp[r] = e & 63;
    }

    float acc[3][4];
#pragma unroll
    for (int nt = 0; nt < 3; ++nt)
#pragma unroll
        for (int q = 0; q < 4; ++q) acc[nt][q] = 0.f;

    float cntAcc = 0.f, sqAcc = 0.f;
    const size_t p0base = (size_t)blockIdx.x * PPB;
    const int rowA0 = 16 * wid + g;

    // ---- prologue: load tile 0 -------------------------------------------
    float4 av[4], bv[4];
    int mreg[5];
#pragma unroll
    for (int i = 0; i < 4; ++i) {
        int c = cr + 16 * i;
        av[i] = *(const float4*)(v1g + (size_t)c * P + p0base + 4 * f4);
        bv[i] = *(const float4*)(v2g + (size_t)c * P + p0base + 4 * f4);
    }
#pragma unroll
    for (int r = 0; r < 5; ++r)
        mreg[r] = masks[(size_t)mk[r] * P + p0base + mp[r]];

    for (int t = 0; t < NT; ++t) {
        const size_t p1 = p0base + (size_t)(t + 1) * TK;
        __syncthreads();   // prev tile's MMA/cnt reads done: s_a, s_bf free

        // ---- Phase A: consume av/bv -> STS raw + squares; prefetch v ------
        float4 pp1 = make_float4(0.f, 0.f, 0.f, 0.f);
        float4 pp2 = make_float4(0.f, 0.f, 0.f, 0.f);
#pragma unroll
        for (int i = 0; i < 4; ++i) {
            int c = cr + 16 * i;
            float4 a = av[i];
            pp1.x = fmaf(a.x, a.x, pp1.x); pp1.y = fmaf(a.y, a.y, pp1.y);
            pp1.z = fmaf(a.z, a.z, pp1.z); pp1.w = fmaf(a.w, a.w, pp1.w);
            *(float4*)&s_a[c * ASTRIDE + 4 * f4] = a;
            float4 b = bv[i];
            pp2.x = fmaf(b.x, b.x, pp2.x); pp2.y = fmaf(b.y, b.y, pp2.y);
            pp2.z = fmaf(b.z, b.z, pp2.z); pp2.w = fmaf(b.w, b.w, pp2.w);
            *(float4*)&s_a[(64 + c) * ASTRIDE + 4 * f4] = b;   // raw v2
        }
        *(float4*)&s_red1[tid * 4] = pp1;
        *(float4*)&s_red2[tid * 4] = pp2;

        if (t + 1 < NT) {
#pragma unroll
            for (int i = 0; i < 4; ++i) {
                int c = cr + 16 * i;
                av[i] = *(const float4*)(v1g + (size_t)c * P + p1 + 4 * f4);
                bv[i] = *(const float4*)(v2g + (size_t)c * P + p1 + 4 * f4);
            }
        }
        __syncthreads();

        // ---- Phase B: reduce per-pixel norms (64 threads) -----------------
        if (tid < TK) {
            int q = tid >> 2, cm = tid & 3;
            float s1 = 0.f, s2 = 0.f;
#pragma unroll
            for (int r = 0; r < 16; ++r) {
                s1 += s_red1[(r * 16 + q) * 4 + cm];
                s2 += s_red2[(r * 16 + q) * 4 + cm];
            }
            s_s1[tid]  = s1;
            s_inv[tid] = 1.0f / fmaxf(sqrtf(s2), EPS);
        }
        __syncthreads();

        // ---- Phase C: rescale v2 in place; build B tile; prefetch masks ---
        {
            float4 iv = *(const float4*)&s_inv[4 * f4];
#pragma unroll
            for (int i = 0; i < 4; ++i) {
                int c = cr + 16 * i;
                float4 b = *(const float4*)&s_a[(64 + c) * ASTRIDE + 4 * f4];
                b.x *= iv.x; b.y *= iv.y; b.z *= iv.z; b.w *= iv.w;
                *(float4*)&s_a[(64 + c) * ASTRIDE + 4 * f4] = b;
            }
        }
#pragma unroll
        for (int r = 0; r < 5; ++r)
            s_bf[mk[r] * ASTRIDE + mp[r]] = (float)(mreg[r] & 1);
        s_bf[(20 + (tid >> 6)) * ASTRIDE + (tid & 63)] = 0.f;   // pad rows

        if (t + 1 < NT) {
#pragma unroll
            for (int r = 0; r < 5; ++r)
                mreg[r] = masks[(size_t)mk[r] * P + p1 + mp[r]];
        }
        __syncthreads();

        // ---- Phase D: MMA over 8 k-steps; cnt/sq on warp 0 ---------------
#pragma unroll
        for (int s = 0; s < 8; ++s) {
            int c0 = 8 * s + tg;
            int c1 = c0 + 4;
            float ra0 = s_a[rowA0 * ASTRIDE + c0];
            float ra1 = s_a[(rowA0 + 8) * ASTRIDE + c0];
            float ra2 = s_a[rowA0 * ASTRIDE + c1];
            float ra3 = s_a[(rowA0 + 8) * ASTRIDE + c1];
            uint32_t h0, l0, h1, l1, h2, l2, h3, l3;
            hi_lo(ra0, h0, l0); hi_lo(ra1, h1, l1);
            hi_lo(ra2, h2, l2); hi_lo(ra3, h3, l3);
#pragma unroll
            for (int nt = 0; nt < 3; ++nt) {
                int n0 = 8 * nt + g;
                uint32_t b0 = __float_as_uint(s_bf[n0 * ASTRIDE + c0]);
                uint32_t b1 = __float_as_uint(s_bf[n0 * ASTRIDE + c1]);
                mma_tf32(acc[nt][0], acc[nt][1], acc[nt][2], acc[nt][3],
                         h0, h1, h2, h3, b0, b1);
                mma_tf32(acc[nt][0], acc[nt][1], acc[nt][2], acc[nt][3],
                         l0, l1, l2, l3, b0, b1);
            }
        }
        if (tid < K) {
            float c0 = 0.f, s0 = 0.f;
#pragma unroll 8
            for (int p = 0; p < TK; ++p) {
                float m = s_bf[tid * ASTRIDE + p];
                c0 += m;
                s0 = fmaf(m, s_s1[p], s0);
            }
            cntAcc += c0;
            sqAcc  += s0;
        }
    }

    // ---- epilogue: atomic accumulation straight into g_red ----------------
    {
        int m0 = rowA0;
        int m1 = rowA0 + 8;
        int off0 = (m0 < 64) ? (OFF_SUM1 + m0) : (OFF_USUM + (m0 - 64));
        int off1 = (m1 < 64) ? (OFF_SUM1 + m1) : (OFF_USUM + (m1 - 64));
#pragma unroll
        for (int nt = 0; nt < 3; ++nt) {
            int n0 = 8 * nt + 2 * tg;
            if (n0 < K) {
                atomicAdd(&g_red[off0 + n0 * C], acc[nt][0]);
                atomicAdd(&g_red[off1 + n0 * C], acc[nt][2]);
            }
            if (n0 + 1 < K) {
                atomicAdd(&g_red[off0 + (n0 + 1) * C], acc[nt][1]);
                atomicAdd(&g_red[off1 + (n0 + 1) * C], acc[nt][3]);
            }
        }
    }
    if (tid < K) {
        atomicAdd(&g_red[OFF_CNT + tid], cntAcc);
        atomicAdd(&g_red[OFF_SQ  + tid], sqAcc);
    }
}

// ---------------------------------------------------------------------------
// Finalize: single block; reads g_red (L2-hot), does small math, writes the
// 34 outputs, then re-zeroes g_red for the next graph replay.
// ---------------------------------------------------------------------------
__global__ void __launch_bounds__(256, 1)
finalize(const int* __restrict__ labels, float* __restrict__ out)
{
    __shared__ float S[PART_STRIDE];
    __shared__ float m1n[K * C];
    __shared__ float simm[K * K];
    __shared__ float stdv[K];
    __shared__ int   s_cls[K];

    const int tid = threadIdx.x;

    for (int i = tid; i < PART_STRIDE; i += 256) S[i] = g_red[i];
    if (tid < K) s_cls[tid] = labels[tid];
    __syncthreads();

    // reset for next replay (S holds the values now)
    for (int i = tid; i < PART_STRIDE; i += 256) g_red[i] = 0.f;

    if (tid < K) {
        const int k = tid;
        float cnt = S[OFF_CNT + k];
        float rc  = 1.0f / cnt;
        float ssum = 0.f;
        for (int cc = 0; cc < C; ++cc) ssum += S[OFF_SUM1 + k * C + cc];
        float n_elem = cnt * (float)C;
        float em  = ssum / n_elem;
        float var = (S[OFF_SQ + k] - n_elem * em * em) / (n_elem - 1.0f);
        stdv[k] = sqrtf(fmaxf(var, 0.0f));

        float nrm2 = 0.f;
        for (int cc = 0; cc < C; ++cc) {
            float m = S[OFF_SUM1 + k * C + cc] * rc;
            m1n[k * C + cc] = m;
            nrm2 = fmaf(m, m, nrm2);
        }
        float inv = 1.0f / fmaxf(sqrtf(nrm2), EPS);
        for (int cc = 0; cc < C; ++cc) m1n[k * C + cc] *= inv;
        for (int cc = 0; cc < C; ++cc) S[OFF_USUM + k * C + cc] *= rc;
    }
    __syncthreads();

    for (int e = tid; e < K * K; e += 256) {
        int ki = e / K;
        int kj = e % K;
        float d = 0.f;
#pragma unroll 8
        for (int cc = 0; cc < C; ++cc)
            d = fmaf(m1n[ki * C + cc], S[OFF_USUM + kj * C + cc], d);
        simm[e] = d;
    }
    __syncthreads();

    if (tid < 32) {
        float ns = 0.f, nc = 0.f;
        for (int e = tid; e < K * K; e += 32) {
            int ki = e / K, kj = e % K;
            if (s_cls[ki] != s_cls[kj]) { ns += simm[e]; nc += 1.0f; }
        }
#pragma unroll
        for (int off = 16; off > 0; off >>= 1) {
            ns += __shfl_xor_sync(0xFFFFFFFFu, ns, off);
            nc += __shfl_xor_sync(0xFFFFFFFFu, nc, off);
        }
        if (tid == 0) out[22] = ns / nc;
    } else if (tid >= 64 && tid < 64 + NUM_CLASSES) {
        const int cl = tid - 64;
        float inst = 0.f, st = 0.f, cs = 0.f, cnt = 0.f;
        for (int ki = 0; ki < K; ++ki) {
            if (s_cls[ki] == cl) {
                inst += simm[ki * K + ki];
                st   += stdv[ki];
                cnt  += 1.0f;
                for (int kj = 0; kj < K; ++kj)
                    if (kj != ki && s_cls[kj] == cl) cs += simm[ki * K + kj];
            }
        }
        if (cnt > 1.0f) {
            inst /= cnt;
            cs   /= cnt * (cnt - 1.0f);
            st   /= cnt;
        }
        out[cl]      = inst;
        out[11 + cl] = cs;
        out[23 + cl] = st;
    }
}

extern "C" void kernel_launch(void* const* d_in, const int* in_sizes, int n_in,
                              void* d_out, int out_size)
{
    const float* v1     = (const float*)d_in[0];
    const float* v2     = (const float*)d_in[1];
    const int*   labels = (const int*)d_in[2];
    const int*   masks  = (const int*)d_in[3];
    float* out = (float*)d_out;

    main_pass<<<NBLOCK, 256, DYN_SZ>>>(v1, v2, masks);
    finalize<<<1, 256>>>(labels, out);
}

// round 12
// speedup vs baseline: 1.5199x; 1.2963x over previous
#include <cuda_runtime.h>
#include <math.h>
#include <stdint.h>

#define C 64
#define P (512 * 512)
#define K 20
#define NUM_CLASSES 11
#define EPS 1e-8f

#define NBLOCK 256
#define PPB (P / NBLOCK)        // 1024 pixels per block
#define TK 64                   // pixels per MMA tile
#define NT (PPB / TK)           // 16 tiles

#define ASTRIDE 68              // padded row stride: MMA-frag LDS conflict-free
#define A_FLOATS (128 * ASTRIDE)
#define RED_FLOATS 2048         // aliased: s_red1|s_red2 (2048) / s_bf (24*68=1632)
#define DYN_SZ ((A_FLOATS + RED_FLOATS) * 4)   // 43008 B < 48K default limit

// reduced sums: sum1[20][64] | usum[20][64] | cnt[20] | sq[20]
#define PART_STRIDE 2600
#define OFF_SUM1 0
#define OFF_USUM 1280
#define OFF_CNT 2560
#define OFF_SQ 2580

static __device__ float g_red[PART_STRIDE];   // zero-init; finalize re-zeroes

// tf32 m16n8k8 row.col MMA (sm_80+, works at compute_100)
__device__ __forceinline__ void mma_tf32(float& d0, float& d1, float& d2, float& d3,
                                         uint32_t a0, uint32_t a1, uint32_t a2, uint32_t a3,
                                         uint32_t b0, uint32_t b1)
{
    asm volatile(
        "mma.sync.aligned.m16n8k8.row.col.f32.tf32.tf32.f32 "
        "{%0,%1,%2,%3}, {%4,%5,%6,%7}, {%8,%9}, {%0,%1,%2,%3};"
        : "+f"(d0), "+f"(d1), "+f"(d2), "+f"(d3)
        : "r"(a0), "r"(a1), "r"(a2), "r"(a3), "r"(b0), "r"(b1));
}

__device__ __forceinline__ void hi_lo(float v, uint32_t& h, uint32_t& l)
{
    uint32_t hu = __float_as_uint(v) & 0xFFFFE000u;   // tf32 truncation
    h = hu;
    l = __float_as_uint(v - __uint_as_float(hu));     // residual
}

// ---------------------------------------------------------------------------
// Main pass: warp-tiled tf32 MMA, software-pipelined (unchanged from R11).
// ---------------------------------------------------------------------------
__global__ void __launch_bounds__(256, 2)
main_pass(const float* __restrict__ v1g,
          const float* __restrict__ v2g,
          const int* __restrict__ masks)
{
    extern __shared__ float dyn[];
    float* s_a    = dyn;                       // [128][68]
    float* s_red1 = dyn + A_FLOATS;            // [1024]   (Phase A-B)
    float* s_red2 = dyn + A_FLOATS + 1024;     // [1024]   (Phase A-B)
    float* s_bf   = dyn + A_FLOATS;            // [24][68] (Phase C-D, aliases s_red)

    __shared__ float s_s1[64];
    __shared__ float s_inv[64];

    const int tid = threadIdx.x;
    const int wid = tid >> 5;
    const int lane = tid & 31;
    const int g  = lane >> 2;
    const int tg = lane & 3;
    const int f4 = tid & 15;
    const int cr = tid >> 4;

    int mk[5], mp[5];
#pragma unroll
    for (int r = 0; r < 5; ++r) {
        int e = tid + 256 * r;
        mk[r] = e >> 6;
        mp[r] = e & 63;
    }

    float acc[3][4];
#pragma unroll
    for (int nt = 0; nt < 3; ++nt)
#pragma unroll
        for (int q = 0; q < 4; ++q) acc[nt][q] = 0.f;

    float cntAcc = 0.f, sqAcc = 0.f;
    const size_t p0base = (size_t)blockIdx.x * PPB;
    const int rowA0 = 16 * wid + g;

    float4 av[4], bv[4];
    int mreg[5];
#pragma unroll
    for (int i = 0; i < 4; ++i) {
        int c = cr + 16 * i;
        av[i] = *(const float4*)(v1g + (size_t)c * P + p0base + 4 * f4);
        bv[i] = *(const float4*)(v2g + (size_t)c * P + p0base + 4 * f4);
    }
#pragma unroll
    for (int r = 0; r < 5; ++r)
        mreg[r] = masks[(size_t)mk[r] * P + p0base + mp[r]];

    for (int t = 0; t < NT; ++t) {
        const size_t p1 = p0base + (size_t)(t + 1) * TK;
        __syncthreads();

        // Phase A
        float4 pp1 = make_float4(0.f, 0.f, 0.f, 0.f);
        float4 pp2 = make_float4(0.f, 0.f, 0.f, 0.f);
#pragma unroll
        for (int i = 0; i < 4; ++i) {
            int c = cr + 16 * i;
            float4 a = av[i];
            pp1.x = fmaf(a.x, a.x, pp1.x); pp1.y = fmaf(a.y, a.y, pp1.y);
            pp1.z = fmaf(a.z, a.z, pp1.z); pp1.w = fmaf(a.w, a.w, pp1.w);
            *(float4*)&s_a[c * ASTRIDE + 4 * f4] = a;
            float4 b = bv[i];
            pp2.x = fmaf(b.x, b.x, pp2.x); pp2.y = fmaf(b.y, b.y, pp2.y);
            pp2.z = fmaf(b.z, b.z, pp2.z); pp2.w = fmaf(b.w, b.w, pp2.w);
            *(float4*)&s_a[(64 + c) * ASTRIDE + 4 * f4] = b;
        }
        *(float4*)&s_red1[tid * 4] = pp1;
        *(float4*)&s_red2[tid * 4] = pp2;

        if (t + 1 < NT) {
#pragma unroll
            for (int i = 0; i < 4; ++i) {
                int c = cr + 16 * i;
                av[i] = *(const float4*)(v1g + (size_t)c * P + p1 + 4 * f4);
                bv[i] = *(const float4*)(v2g + (size_t)c * P + p1 + 4 * f4);
            }
        }
        __syncthreads();

        // Phase B
        if (tid < TK) {
            int q = tid >> 2, cm = tid & 3;
            float s1 = 0.f, s2 = 0.f;
#pragma unroll
            for (int r = 0; r < 16; ++r) {
                s1 += s_red1[(r * 16 + q) * 4 + cm];
                s2 += s_red2[(r * 16 + q) * 4 + cm];
            }
            s_s1[tid]  = s1;
            s_inv[tid] = 1.0f / fmaxf(sqrtf(s2), EPS);
        }
        __syncthreads();

        // Phase C
        {
            float4 iv = *(const float4*)&s_inv[4 * f4];
#pragma unroll
            for (int i = 0; i < 4; ++i) {
                int c = cr + 16 * i;
                float4 b = *(const float4*)&s_a[(64 + c) * ASTRIDE + 4 * f4];
                b.x *= iv.x; b.y *= iv.y; b.z *= iv.z; b.w *= iv.w;
                *(float4*)&s_a[(64 + c) * ASTRIDE + 4 * f4] = b;
            }
        }
#pragma unroll
        for (int r = 0; r < 5; ++r)
            s_bf[mk[r] * ASTRIDE + mp[r]] = (float)(mreg[r] & 1);
        s_bf[(20 + (tid >> 6)) * ASTRIDE + (tid & 63)] = 0.f;

        if (t + 1 < NT) {
#pragma unroll
            for (int r = 0; r < 5; ++r)
                mreg[r] = masks[(size_t)mk[r] * P + p1 + mp[r]];
        }
        __syncthreads();

        // Phase D
#pragma unroll
        for (int s = 0; s < 8; ++s) {
            int c0 = 8 * s + tg;
            int c1 = c0 + 4;
            float ra0 = s_a[rowA0 * ASTRIDE + c0];
            float ra1 = s_a[(rowA0 + 8) * ASTRIDE + c0];
            float ra2 = s_a[rowA0 * ASTRIDE + c1];
            float ra3 = s_a[(rowA0 + 8) * ASTRIDE + c1];
            uint32_t h0, l0, h1, l1, h2, l2, h3, l3;
            hi_lo(ra0, h0, l0); hi_lo(ra1, h1, l1);
            hi_lo(ra2, h2, l2); hi_lo(ra3, h3, l3);
#pragma unroll
            for (int nt = 0; nt < 3; ++nt) {
                int n0 = 8 * nt + g;
                uint32_t b0 = __float_as_uint(s_bf[n0 * ASTRIDE + c0]);
                uint32_t b1 = __float_as_uint(s_bf[n0 * ASTRIDE + c1]);
                mma_tf32(acc[nt][0], acc[nt][1], acc[nt][2], acc[nt][3],
                         h0, h1, h2, h3, b0, b1);
                mma_tf32(acc[nt][0], acc[nt][1], acc[nt][2], acc[nt][3],
                         l0, l1, l2, l3, b0, b1);
            }
        }
        if (tid < K) {
            float c0 = 0.f, s0 = 0.f;
#pragma unroll 8
            for (int p = 0; p < TK; ++p) {
                float m = s_bf[tid * ASTRIDE + p];
                c0 += m;
                s0 = fmaf(m, s_s1[p], s0);
            }
            cntAcc += c0;
            sqAcc  += s0;
        }
    }

    // epilogue: atomics straight into g_red
    {
        int m0 = rowA0;
        int m1 = rowA0 + 8;
        int off0 = (m0 < 64) ? (OFF_SUM1 + m0) : (OFF_USUM + (m0 - 64));
        int off1 = (m1 < 64) ? (OFF_SUM1 + m1) : (OFF_USUM + (m1 - 64));
#pragma unroll
        for (int nt = 0; nt < 3; ++nt) {
            int n0 = 8 * nt + 2 * tg;
            if (n0 < K) {
                atomicAdd(&g_red[off0 + n0 * C], acc[nt][0]);
                atomicAdd(&g_red[off1 + n0 * C], acc[nt][2]);
            }
            if (n0 + 1 < K) {
                atomicAdd(&g_red[off0 + (n0 + 1) * C], acc[nt][1]);
                atomicAdd(&g_red[off1 + (n0 + 1) * C], acc[nt][3]);
            }
        }
    }
    if (tid < K) {
        atomicAdd(&g_red[OFF_CNT + tid], cntAcc);
        atomicAdd(&g_red[OFF_SQ  + tid], sqAcc);
    }
}

// ---------------------------------------------------------------------------
// Finalize: 1024 threads, latency-parallelized small math.
//  - warp per instance k (warps 0-19): stats via lane-split + butterfly
//  - 400 threads: sim dots with 4-way split accumulators
//  - warp 0: negsum; warps 1-11: warp per class, lane-split over instances
// All reductions are fixed-order butterflies -> deterministic.
// ---------------------------------------------------------------------------
__global__ void __launch_bounds__(1024, 1)
finalize(const int* __restrict__ labels, float* __restrict__ out)
{
    __shared__ float S[PART_STRIDE];
    __shared__ float m1n[K * C];
    __shared__ float simm[K * K];
    __shared__ float stdv[K];
    __shared__ int   s_cls[K];

    const int tid = threadIdx.x;
    const int wid = tid >> 5;
    const int lane = tid & 31;

    for (int i = tid; i < PART_STRIDE; i += 1024) S[i] = g_red[i];
    if (tid < K) s_cls[tid] = labels[tid];
    __syncthreads();

    // reset for next replay (S holds the values now)
    for (int i = tid; i < PART_STRIDE; i += 1024) g_red[i] = 0.f;

    // ---- per-instance stats: warp per k ----------------------------------
    if (wid < K) {
        const int k = wid;
        float cnt = S[OFF_CNT + k];
        float rc  = 1.0f / cnt;
        float s0 = S[OFF_SUM1 + k * C + lane];
        float s1 = S[OFF_SUM1 + k * C + lane + 32];
        float ssum = s0 + s1;
        float m0 = s0 * rc, m1 = s1 * rc;
        float nrm2 = fmaf(m0, m0, m1 * m1);
#pragma unroll
        for (int off = 16; off > 0; off >>= 1) {
            ssum += __shfl_xor_sync(0xFFFFFFFFu, ssum, off);
            nrm2 += __shfl_xor_sync(0xFFFFFFFFu, nrm2, off);
        }
        float n_elem = cnt * (float)C;
        float em  = ssum / n_elem;
        if (lane == 0) {
            float var = (S[OFF_SQ + k] - n_elem * em * em) / (n_elem - 1.0f);
            stdv[k] = sqrtf(fmaxf(var, 0.0f));
        }
        float inv = 1.0f / fmaxf(sqrtf(nrm2), EPS);
        m1n[k * C + lane]      = m0 * inv;
        m1n[k * C + lane + 32] = m1 * inv;
        S[OFF_USUM + k * C + lane]      *= rc;
        S[OFF_USUM + k * C + lane + 32] *= rc;
    }
    __syncthreads();

    // ---- sim[ki][kj]: 400 threads, 4-way split accumulators --------------
    if (tid < K * K) {
        int ki = tid / K;
        int kj = tid - ki * K;
        const float* a = &m1n[ki * C];
        const float* b = &S[OFF_USUM + kj * C];
        float d0 = 0.f, d1 = 0.f, d2 = 0.f, d3 = 0.f;
#pragma unroll
        for (int cc = 0; cc < C; cc += 4) {
            d0 = fmaf(a[cc],     b[cc],     d0);
            d1 = fmaf(a[cc + 1], b[cc + 1], d1);
            d2 = fmaf(a[cc + 2], b[cc + 2], d2);
            d3 = fmaf(a[cc + 3], b[cc + 3], d3);
        }
        simm[tid] = (d0 + d1) + (d2 + d3);
    }
    __syncthreads();

    if (wid == 0) {
        // negsum: lane-strided, fixed-order butterfly
        float ns = 0.f, nc = 0.f;
        for (int e = lane; e < K * K; e += 32) {
            int ki = e / K, kj = e - ki * K;
            if (s_cls[ki] != s_cls[kj]) { ns += simm[e]; nc += 1.0f; }
        }
#pragma unroll
        for (int off = 16; off > 0; off >>= 1) {
            ns += __shfl_xor_sync(0xFFFFFFFFu, ns, off);
            nc += __shfl_xor_sync(0xFFFFFFFFu, nc, off);
        }
        if (lane == 0) out[22] = ns / nc;
    } else if (wid <= NUM_CLASSES) {
        // warp per class: lanes split instances ki (lane < 20 active)
        const int cl = wid - 1;
        float inst = 0.f, st = 0.f, cs = 0.f, cnt = 0.f;
        if (lane < K && s_cls[lane] == cl) {
            const int ki = lane;
            inst = simm[ki * K + ki];
            st   = stdv[ki];
            cnt  = 1.0f;
#pragma unroll
            for (int kj = 0; kj < K; ++kj)
                if (kj != ki && s_cls[kj] == cl) cs += simm[ki * K + kj];
        }
#pragma unroll
        for (int off = 16; off > 0; off >>= 1) {
            inst += __shfl_xor_sync(0xFFFFFFFFu, inst, off);
            st   += __shfl_xor_sync(0xFFFFFFFFu, st,   off);
            cs   += __shfl_xor_sync(0xFFFFFFFFu, cs,   off);
            cnt  += __shfl_xor_sync(0xFFFFFFFFu, cnt,  off);
        }
        if (lane == 0) {
            if (cnt > 1.0f) {
                inst /= cnt;
                cs   /= cnt * (cnt - 1.0f);
                st   /= cnt;
            }
            out[cl]      = inst;
            out[11 + cl] = cs;
            out[23 + cl] = st;
        }
    }
}

extern "C" void kernel_launch(void* const* d_in, const int* in_sizes, int n_in,
                              void* d_out, int out_size)
{
    const float* v1     = (const float*)d_in[0];
    const float* v2     = (const float*)d_in[1];
    const int*   labels = (const int*)d_in[2];
    const int*   masks  = (const int*)d_in[3];
    float* out = (float*)d_out;

    main_pass<<<NBLOCK, 256, DYN_SZ>>>(v1, v2, masks);
    finalize<<<1, 1024>>>(labels, out);
}

// round 15
// speedup vs baseline: 1.5804x; 1.0398x over previous
#include <cuda_runtime.h>
#include <math.h>
#include <stdint.h>

#define C 64
#define P (512 * 512)
#define K 20
#define NUM_CLASSES 11
#define EPS 1e-8f

#define GRID 296                 // 2 CTAs x 148 SMs, perfectly balanced
#define TK 64                    // pixels per MMA tile
#define TOTAL_TILES (P / TK)     // 4096
#define BASE_TILES (TOTAL_TILES / GRID)          // 13
#define EXTRA (TOTAL_TILES - GRID * BASE_TILES)  // 248 blocks get 14

#define ASTRIDE 68               // padded row stride: MMA-frag LDS conflict-free
#define A_FLOATS (128 * ASTRIDE)
#define RED_FLOATS 2048          // aliased: s_red1|s_red2 (2048) / s_bf (24*68=1632)
#define DYN_FLOATS (A_FLOATS + RED_FLOATS)
#define DYN_SZ (DYN_FLOATS * 4)  // 43008 B < 48K default limit

// reduced sums: sum1[20][64] | usum[20][64] | cnt[20] | sq[20]
#define PART_STRIDE 2600
#define OFF_SUM1 0
#define OFF_USUM 1280
#define OFF_CNT 2560
#define OFF_SQ 2580

static __device__ float g_red[PART_STRIDE];   // zero-init; finalize tail re-zeroes
static __device__ unsigned int g_ticket;      // zero-init; finalize tail resets

// tf32 m16n8k8 row.col MMA (sm_80+, works at compute_100)
__device__ __forceinline__ void mma_tf32(float& d0, float& d1, float& d2, float& d3,
                                         uint32_t a0, uint32_t a1, uint32_t a2, uint32_t a3,
                                         uint32_t b0, uint32_t b1)
{
    asm volatile(
        "mma.sync.aligned.m16n8k8.row.col.f32.tf32.tf32.f32 "
        "{%0,%1,%2,%3}, {%4,%5,%6,%7}, {%8,%9}, {%0,%1,%2,%3};"
        : "+f"(d0), "+f"(d1), "+f"(d2), "+f"(d3)
        : "r"(a0), "r"(a1), "r"(a2), "r"(a3), "r"(b0), "r"(b1));
}

__device__ __forceinline__ void hi_lo(float v, uint32_t& h, uint32_t& l)
{
    uint32_t hu = __float_as_uint(v) & 0xFFFFE000u;   // tf32 truncation
    h = hu;
    l = __float_as_uint(v - __uint_as_float(hu));     // residual
}

// ---------------------------------------------------------------------------
// Single fused kernel.
// Main loop: warp-tiled tf32 MMA, software-pipelined, grid-strided tiles
// (block b does tiles b, b+296, ... -> 13 or 14 tiles). Epilogue atomics into
// g_red. Threadfence-ticket: LAST block runs the warp-parallel finalize using
// the (now dead) dynamic smem region as scratch.
// ---------------------------------------------------------------------------
__global__ void __launch_bounds__(256, 2)
fused_kernel(const float* __restrict__ v1g,
             const float* __restrict__ v2g,
             const int* __restrict__ masks,
             const int* __restrict__ labels,
             float* __restrict__ out)
{
    extern __shared__ float dyn[];
    float* s_a    = dyn;                       // [128][68]
    float* s_red1 = dyn + A_FLOATS;            // [1024]   (Phase A-B)
    float* s_red2 = dyn + A_FLOATS + 1024;     // [1024]   (Phase A-B)
    float* s_bf   = dyn + A_FLOATS;            // [24][68] (Phase C-D, aliases s_red)

    __shared__ float s_s1[64];
    __shared__ float s_inv[64];
    __shared__ unsigned int isLast;

    const int tid = threadIdx.x;
    const int wid = tid >> 5;
    const int lane = tid & 31;
    const int g  = lane >> 2;
    const int tg = lane & 3;
    const int f4 = tid & 15;
    const int cr = tid >> 4;

    int mk[5], mp[5];
#pragma unroll
    for (int r = 0; r < 5; ++r) {
        int e = tid + 256 * r;
        mk[r] = e >> 6;
        mp[r] = e & 63;
    }

    float acc[3][4];
#pragma unroll
    for (int nt = 0; nt < 3; ++nt)
#pragma unroll
        for (int q = 0; q < 4; ++q) acc[nt][q] = 0.f;

    float cntAcc = 0.f, sqAcc = 0.f;
    const int nTiles = BASE_TILES + (blockIdx.x < EXTRA ? 1 : 0);
    const int rowA0 = 16 * wid + g;
    size_t p0 = (size_t)blockIdx.x * TK;       // tile stride = GRID*TK

    // ---- prologue: load tile 0 -------------------------------------------
    float4 av[4], bv[4];
    int mreg[5];
#pragma unroll
    for (int i = 0; i < 4; ++i) {
        int c = cr + 16 * i;
        av[i] = *(const float4*)(v1g + (size_t)c * P + p0 + 4 * f4);
        bv[i] = *(const float4*)(v2g + (size_t)c * P + p0 + 4 * f4);
    }
#pragma unroll
    for (int r = 0; r < 5; ++r)
        mreg[r] = masks[(size_t)mk[r] * P + p0 + mp[r]];

    for (int t = 0; t < nTiles; ++t) {
        const size_t p1 = p0 + (size_t)GRID * TK;
        __syncthreads();

        // Phase A
        float4 pp1 = make_float4(0.f, 0.f, 0.f, 0.f);
        float4 pp2 = make_float4(0.f, 0.f, 0.f, 0.f);
#pragma unroll
        for (int i = 0; i < 4; ++i) {
            int c = cr + 16 * i;
            float4 a = av[i];
            pp1.x = fmaf(a.x, a.x, pp1.x); pp1.y = fmaf(a.y, a.y, pp1.y);
            pp1.z = fmaf(a.z, a.z, pp1.z); pp1.w = fmaf(a.w, a.w, pp1.w);
            *(float4*)&s_a[c * ASTRIDE + 4 * f4] = a;
            float4 b = bv[i];
            pp2.x = fmaf(b.x, b.x, pp2.x); pp2.y = fmaf(b.y, b.y, pp2.y);
            pp2.z = fmaf(b.z, b.z, pp2.z); pp2.w = fmaf(b.w, b.w, pp2.w);
            *(float4*)&s_a[(64 + c) * ASTRIDE + 4 * f4] = b;
        }
        *(float4*)&s_red1[tid * 4] = pp1;
        *(float4*)&s_red2[tid * 4] = pp2;

        if (t + 1 < nTiles) {
#pragma unroll
            for (int i = 0; i < 4; ++i) {
                int c = cr + 16 * i;
                av[i] = *(const float4*)(v1g + (size_t)c * P + p1 + 4 * f4);
                bv[i] = *(const float4*)(v2g + (size_t)c * P + p1 + 4 * f4);
            }
        }
        __syncthreads();

        // Phase B
        if (tid < TK) {
            int q = tid >> 2, cm = tid & 3;
            float s1 = 0.f, s2 = 0.f;
#pragma unroll
            for (int r = 0; r < 16; ++r) {
                s1 += s_red1[(r * 16 + q) * 4 + cm];
                s2 += s_red2[(r * 16 + q) * 4 + cm];
            }
            s_s1[tid]  = s1;
            s_inv[tid] = 1.0f / fmaxf(sqrtf(s2), EPS);
        }
        __syncthreads();

        // Phase C
        {
            float4 iv = *(const float4*)&s_inv[4 * f4];
#pragma unroll
            for (int i = 0; i < 4; ++i) {
                int c = cr + 16 * i;
                float4 b = *(const float4*)&s_a[(64 + c) * ASTRIDE + 4 * f4];
                b.x *= iv.x; b.y *= iv.y; b.z *= iv.z; b.w *= iv.w;
                *(float4*)&s_a[(64 + c) * ASTRIDE + 4 * f4] = b;
            }
        }
#pragma unroll
        for (int r = 0; r < 5; ++r)
            s_bf[mk[r] * ASTRIDE + mp[r]] = (float)(mreg[r] & 1);
        s_bf[(20 + (tid >> 6)) * ASTRIDE + (tid & 63)] = 0.f;

        if (t + 1 < nTiles) {
#pragma unroll
            for (int r = 0; r < 5; ++r)
                mreg[r] = masks[(size_t)mk[r] * P + p1 + mp[r]];
        }
        __syncthreads();

        // Phase D
#pragma unroll
        for (int s = 0; s < 8; ++s) {
            int c0 = 8 * s + tg;
            int c1 = c0 + 4;
            float ra0 = s_a[rowA0 * ASTRIDE + c0];
            float ra1 = s_a[(rowA0 + 8) * ASTRIDE + c0];
            float ra2 = s_a[rowA0 * ASTRIDE + c1];
            float ra3 = s_a[(rowA0 + 8) * ASTRIDE + c1];
            uint32_t h0, l0, h1, l1, h2, l2, h3, l3;
            hi_lo(ra0, h0, l0); hi_lo(ra1, h1, l1);
            hi_lo(ra2, h2, l2); hi_lo(ra3, h3, l3);
#pragma unroll
            for (int nt = 0; nt < 3; ++nt) {
                int n0 = 8 * nt + g;
                uint32_t b0 = __float_as_uint(s_bf[n0 * ASTRIDE + c0]);
                uint32_t b1 = __float_as_uint(s_bf[n0 * ASTRIDE + c1]);
                mma_tf32(acc[nt][0], acc[nt][1], acc[nt][2], acc[nt][3],
                         h0, h1, h2, h3, b0, b1);
                mma_tf32(acc[nt][0], acc[nt][1], acc[nt][2], acc[nt][3],
                         l0, l1, l2, l3, b0, b1);
            }
        }
        if (tid < K) {
            float c0 = 0.f, s0 = 0.f;
#pragma unroll 8
            for (int p = 0; p < TK; ++p) {
                float m = s_bf[tid * ASTRIDE + p];
                c0 += m;
                s0 = fmaf(m, s_s1[p], s0);
            }
            cntAcc += c0;
            sqAcc  += s0;
        }
        p0 = p1;
    }

    // ---- epilogue: atomics into g_red -------------------------------------
    {
        int m0 = rowA0;
        int m1 = rowA0 + 8;
        int off0 = (m0 < 64) ? (OFF_SUM1 + m0) : (OFF_USUM + (m0 - 64));
        int off1 = (m1 < 64) ? (OFF_SUM1 + m1) : (OFF_USUM + (m1 - 64));
#pragma unroll
        for (int nt = 0; nt < 3; ++nt) {
            int n0 = 8 * nt + 2 * tg;
            if (n0 < K) {
                atomicAdd(&g_red[off0 + n0 * C], acc[nt][0]);
                atomicAdd(&g_red[off1 + n0 * C], acc[nt][2]);
            }
            if (n0 + 1 < K) {
                atomicAdd(&g_red[off0 + (n0 + 1) * C], acc[nt][1]);
                atomicAdd(&g_red[off1 + (n0 + 1) * C], acc[nt][3]);
            }
        }
    }
    if (tid < K) {
        atomicAdd(&g_red[OFF_CNT + tid], cntAcc);
        atomicAdd(&g_red[OFF_SQ  + tid], sqAcc);
    }

    // ---- ticket: last block finalizes -------------------------------------
    __syncthreads();
    if (tid == 0) {
        __threadfence();
        unsigned int tk = atomicAdd(&g_ticket, 1u);
        isLast = (tk == (unsigned int)(GRID - 1)) ? 1u : 0u;
    }
    __syncthreads();
    if (!isLast) return;
    __threadfence();

    // ---- finalize (256 threads; scratch in dead dynamic smem) -------------
    float* S    = dyn;             // [2600]
    float* m1n  = dyn + 2600;      // [K*C]
    float* simm = dyn + 3880;      // [K*K]
    __shared__ float stdv[K];
    __shared__ int   s_cls[K];

    for (int i = tid; i < PART_STRIDE; i += 256) S[i] = g_red[i];
    if (tid < K) s_cls[tid] = labels[tid];
    __syncthreads();

    // reset globals for next graph replay (S holds the values now)
    for (int i = tid; i < PART_STRIDE; i += 256) g_red[i] = 0.f;
    if (tid == 0) g_ticket = 0u;

    // per-instance stats: warp per k, 3 rounds
    for (int k = wid; k < K; k += 8) {
        float cnt = S[OFF_CNT + k];
        float rc  = 1.0f / cnt;
        float v0 = S[OFF_SUM1 + k * C + lane];
        float v1 = S[OFF_SUM1 + k * C + lane + 32];
        float ssum = v0 + v1;
        float m0 = v0 * rc, m1 = v1 * rc;
        float nrm2 = fmaf(m0, m0, m1 * m1);
#pragma unroll
        for (int off = 16; off > 0; off >>= 1) {
            ssum += __shfl_xor_sync(0xFFFFFFFFu, ssum, off);
            nrm2 += __shfl_xor_sync(0xFFFFFFFFu, nrm2, off);
        }
        float n_elem = cnt * (float)C;
        float em  = ssum / n_elem;
        if (lane == 0) {
            float var = (S[OFF_SQ + k] - n_elem * em * em) / (n_elem - 1.0f);
            stdv[k] = sqrtf(fmaxf(var, 0.0f));
        }
        float inv = 1.0f / fmaxf(sqrtf(nrm2), EPS);
        m1n[k * C + lane]      = m0 * inv;
        m1n[k * C + lane + 32] = m1 * inv;
        S[OFF_USUM + k * C + lane]      *= rc;
        S[OFF_USUM + k * C + lane + 32] *= rc;
    }
    __syncthreads();

    // sim dots: 400 over 256 threads, 4-way split accumulators
    for (int e = tid; e < K * K; e += 256) {
        int ki = e / K;
        int kj = e - ki * K;
        const float* a = &m1n[ki * C];
        const float* b = &S[OFF_USUM + kj * C];
        float d0 = 0.f, d1 = 0.f, d2 = 0.f, d3 = 0.f;
#pragma unroll
        for (int cc = 0; cc < C; cc += 4) {
            d0 = fmaf(a[cc],     b[cc],     d0);
            d1 = fmaf(a[cc + 1], b[cc + 1], d1);
            d2 = fmaf(a[cc + 2], b[cc + 2], d2);
            d3 = fmaf(a[cc + 3], b[cc + 3], d3);
        }
        simm[e] = (d0 + d1) + (d2 + d3);
    }
    __syncthreads();

    if (wid == 0) {
        float ns = 0.f, nc = 0.f;
        for (int e = lane; e < K * K; e += 32) {
            int ki = e / K, kj = e - ki * K;
            if (s_cls[ki] != s_cls[kj]) { ns += simm[e]; nc += 1.0f; }
        }
#pragma unroll
        for (int off = 16; off > 0; off >>= 1) {
            ns += __shfl_xor_sync(0xFFFFFFFFu, ns, off);
            nc += __shfl_xor_sync(0xFFFFFFFFu, nc, off);
        }
        if (lane == 0) out[22] = ns / nc;
    } else {
        // warps 1-7: classes cl = wid-1, wid+6
        for (int cl = wid - 1; cl < NUM_CLASSES; cl += 7) {
            float inst = 0.f, st = 0.f, cs = 0.f, cnt = 0.f;
            if (lane < K && s_cls[lane] == cl) {
                const int ki = lane;
                inst = simm[ki * K + ki];
                st   = stdv[ki];
                cnt  = 1.0f;
#pragma unroll
                for (int kj = 0; kj < K; ++kj)
                    if (kj != ki && s_cls[kj] == cl) cs += simm[ki * K + kj];
            }
#pragma unroll
            for (int off = 16; off > 0; off >>= 1) {
                inst += __shfl_xor_sync(0xFFFFFFFFu, inst, off);
                st   += __shfl_xor_sync(0xFFFFFFFFu, st,   off);
                cs   += __shfl_xor_sync(0xFFFFFFFFu, cs,   off);
                cnt  += __shfl_xor_sync(0xFFFFFFFFu, cnt,  off);
            }
            if (lane == 0) {
                if (cnt > 1.0f) {
                    inst /= cnt;
                    cs   /= cnt * (cnt - 1.0f);
                    st   /= cnt;
                }
                out[cl]      = inst;
                out[11 + cl] = cs;
                out[23 + cl] = st;
            }
        }
    }
}

extern "C" void kernel_launch(void* const* d_in, const int* in_sizes, int n_in,
                              void* d_out, int out_size)
{
    const float* v1     = (const float*)d_in[0];
    const float* v2     = (const float*)d_in[1];
    const int*   labels = (const int*)d_in[2];
    const int*   masks  = (const int*)d_in[3];
    float* out = (float*)d_out;

    fused_kernel<<<GRID, 256, DYN_SZ>>>(v1, v2, masks, labels, out);
}